// round 17
// baseline (speedup 1.0000x reference)
#include <cuda_runtime.h>

// R17: R16 (37.4us best) with the divergent q1-if converted to branchless
// bias masking. Loop split: A) fixed 16 iterations, dual body, q1's score
// chain gets an additive -200 bias via 64-bit SEL when i>=np1 (exp -> 0
// under FTZ; no BSSY/BSYNC reconvergence per iteration); B) q2-only loop
// i in [16, np2), exit-only divergence. Everything else identical to R16:
// table-hoisted prologue, dual-query lanes, (256,4) launch bounds,
// smem-staged coalesced logits store.

#define T 64
#define WPB 8                      // warps = batches per block
#define NTHREADS (WPB * 32)
#define VOCAB 10

typedef unsigned long long u64;

__device__ float4 g_q4[VOCAB * T];   // scaled RoPE'd Q
__device__ float4 g_k4[VOCAB * T];   // RoPE'd K
__device__ float4 g_v4[VOCAB * T];   // (vq0, vq1, vq2, unused) = v @ Wq

__device__ __forceinline__ float ex2f(float x) {
    float y; asm("ex2.approx.ftz.f32 %0, %1;" : "=f"(y) : "f"(x)); return y;
}
__device__ __forceinline__ float rcpf(float x) {
    float y; asm("rcp.approx.ftz.f32 %0, %1;" : "=f"(y) : "f"(x)); return y;
}
__device__ __forceinline__ u64 pack2(float lo, float hi) {
    u64 r; asm("mov.b64 %0, {%1, %2};" : "=l"(r) : "f"(lo), "f"(hi)); return r;
}
__device__ __forceinline__ void unpack2(u64 v, float& lo, float& hi) {
    asm("mov.b64 {%0, %1}, %2;" : "=f"(lo), "=f"(hi) : "l"(v));
}
__device__ __forceinline__ u64 fma2(u64 a, u64 b, u64 c) {
    u64 d; asm("fma.rn.f32x2 %0, %1, %2, %3;" : "=l"(d) : "l"(a), "l"(b), "l"(c)); return d;
}
__device__ __forceinline__ u64 mul2(u64 a, u64 b) {
    u64 d; asm("mul.rn.f32x2 %0, %1, %2;" : "=l"(d) : "l"(a), "l"(b)); return d;
}
__device__ __forceinline__ u64 add2(u64 a, u64 b) {
    u64 d; asm("add.rn.f32x2 %0, %1, %2;" : "=l"(d) : "l"(a), "l"(b)); return d;
}

// ---------------- kernel 1: 640-entry AoS tables ----------------
__global__ void precompute_kernel(
    const float* __restrict__ pA,
    const float* __restrict__ pS,
    const float* __restrict__ pD,
    const float* __restrict__ w_ln1,
    const float* __restrict__ w_qn,
    const float* __restrict__ Wq,
    const float* __restrict__ Wk)
{
    const int dig = blockIdx.x;    // 0..9
    const int t   = threadIdx.x;   // 0..63

    const float A = pA[0], ast = pS[0], astr = pD[0];
    float sa, ca;
    __sincosf(ast + (float)dig * astr, &sa, &ca);
    const float x0 = A * ca;
    const float x1 = A * sa;
    const float x2 = __sinf((float)t * 1.0e-4f);

    const float r = rsqrtf((x0*x0 + x1*x1 + x2*x2) * (1.0f/3.0f) + 1e-6f);
    const float h0 = x0 * r * w_ln1[0];
    const float h1 = x1 * r * w_ln1[1];
    const float h2 = x2 * r * w_ln1[2];

    float qr[4], kv[4];
#pragma unroll
    for (int j = 0; j < 4; ++j) {
        qr[j] = h0 * Wq[j*3+0] + h1 * Wq[j*3+1] + h2 * Wq[j*3+2];
        kv[j] = h0 * Wk[j*3+0] + h1 * Wk[j*3+1] + h2 * Wk[j*3+2];
    }

    const float vq0 = kv[0]*Wq[0] + kv[1]*Wq[3] + kv[2]*Wq[6] + kv[3]*Wq[9];
    const float vq1 = kv[0]*Wq[1] + kv[1]*Wq[4] + kv[2]*Wq[7] + kv[3]*Wq[10];
    const float vq2 = kv[0]*Wq[2] + kv[1]*Wq[5] + kv[2]*Wq[8] + kv[3]*Wq[11];

    const float rq = rsqrtf((qr[0]*qr[0]+qr[1]*qr[1]+qr[2]*qr[2]+qr[3]*qr[3]) * 0.25f + 1e-6f);
    const float rk = rsqrtf((kv[0]*kv[0]+kv[1]*kv[1]+kv[2]*kv[2]+kv[3]*kv[3]) * 0.25f + 1e-6f);
    const float q0 = qr[0]*rq*w_qn[0], q1 = qr[1]*rq*w_qn[1];
    const float q2 = qr[2]*rq*w_qn[2], q3 = qr[3]*rq*w_qn[3];
    const float k0 = kv[0]*rk*w_qn[0], k1 = kv[1]*rk*w_qn[1];
    const float k2 = kv[2]*rk*w_qn[2], k3 = kv[3]*rk*w_qn[3];

    float s0, c0, s1, c1;
    __sincosf((float)t, &s0, &c0);
    __sincosf((float)t * 0.57735026918962576f, &s1, &c1);

    const float SC = 0.5f * 1.4426950408889634f;   // scale * log2(e)
    const int e = dig * T + t;
    g_q4[e] = make_float4((q0*c0 - q1*s0)*SC, (q0*s0 + q1*c0)*SC,
                          (q2*c1 - q3*s1)*SC, (q2*s1 + q3*c1)*SC);
    g_k4[e] = make_float4(k0*c0 - k1*s0, k0*s0 + k1*c0,
                          k2*c1 - k3*s1, k2*s1 + k3*c1);
    g_v4[e] = make_float4(vq0, vq1, vq2, 0.0f);
}

// ---------------- kernel 2: attention + FFN + logits ----------------
__global__ __launch_bounds__(NTHREADS, 4)
void adder_model_kernel(
    const int* __restrict__ idx,
    const float* __restrict__ pA,
    const float* __restrict__ pStart,
    const float* __restrict__ pStride,
    const float* __restrict__ w_ln2,
    const float* __restrict__ w_lnf,
    const float* __restrict__ Wg,
    const float* __restrict__ Wu,
    const float* __restrict__ Wd,
    float* __restrict__ out)
{
    __shared__ ulonglong2 kA[WPB][T / 2];
    __shared__ ulonglong2 kB[WPB][T / 2];
    __shared__ ulonglong2 vA[WPB][T / 2];   // (vq0 pair, vq1 pair)
    __shared__ u64        vC[WPB][T / 2];   // vq2 pair
    __shared__ float2 table_sh[VOCAB];
    __shared__ float  logits_sh[WPB * T * VOCAB];

    const int tid  = threadIdx.x;
    const int w    = tid >> 5;           // warp = batch within block
    const int lane = tid & 31;
    const int b    = blockIdx.x * WPB + w;

    if (tid < VOCAB) {
        float s, c;
        __sincosf(pStart[0] + (float)tid * pStride[0], &s, &c);
        const float A = pA[0];
        table_sh[tid] = make_float2(A * c, A * s);
    }

    // ---- prologue: two tokens per lane, 3 gathers each ----
    u64 Qd[2][4];
    int digs[2];

#pragma unroll
    for (int tk = 0; tk < 2; ++tk) {
        const int t = lane + 32 * tk;
        const int dig = idx[(size_t)b * T + t];
        digs[tk] = dig;
        const int e = dig * T + t;

        const float4 q = g_q4[e];
        const float4 k = g_k4[e];
        const float4 v = g_v4[e];

        Qd[tk][0] = pack2(q.x, q.x); Qd[tk][1] = pack2(q.y, q.y);
        Qd[tk][2] = pack2(q.z, q.z); Qd[tk][3] = pack2(q.w, q.w);

        const int i = t >> 1, par = t & 1;
        float* a = (float*)&kA[w][i]; a[par] = k.x; a[2 + par] = k.y;
        float* bb = (float*)&kB[w][i]; bb[par] = k.z; bb[2 + par] = k.w;
        float* c = (float*)&vA[w][i]; c[par] = v.x; c[2 + par] = v.y;
        float* d = (float*)&vC[w][i]; d[par] = v.z;
    }
    __syncthreads();

    // ---- dual-query loop, branchless q1 masking ----
    const int np1 = (lane + 1) >> 1;        // prefix bound for t1 = lane   (0..16)
    const int np2 = (lane + 33) >> 1;       // prefix bound for t2 = lane+32 (16..32)
    const u64 M200 = pack2(-200.0f, -200.0f);

    u64 s1d = 0ULL, a1x = 0ULL, a1y = 0ULL, a1z = 0ULL;
    u64 s2d = 0ULL, a2x = 0ULL, a2y = 0ULL, a2z = 0ULL;

    // loop A: i in [0,16), fixed bound; q1 masked by additive bias (no branch)
#pragma unroll 4
    for (int i = 0; i < 16; ++i) {
        const ulonglong2 ka = kA[w][i];
        const ulonglong2 kb = kB[w][i];
        const ulonglong2 va = vA[w][i];
        const u64 vc = vC[w][i];

        // q2 (always active)
        {
            const u64 sc = fma2(Qd[1][0], ka.x, fma2(Qd[1][1], ka.y,
                           fma2(Qd[1][2], kb.x, mul2(Qd[1][3], kb.y))));
            float sl, sh; unpack2(sc, sl, sh);
            const u64 p = pack2(ex2f(sl), ex2f(sh));
            s2d = add2(s2d, p);
            a2x = fma2(p, va.x, a2x);
            a2y = fma2(p, va.y, a2y);
            a2z = fma2(p, vc,   a2z);
        }
        // q1 (bias-masked: exp(score-200) flushes to 0)
        {
            const u64 mb = (i < np1) ? 0ULL : M200;
            const u64 sc = fma2(Qd[0][0], ka.x, fma2(Qd[0][1], ka.y,
                           fma2(Qd[0][2], kb.x, fma2(Qd[0][3], kb.y, mb))));
            float sl, sh; unpack2(sc, sl, sh);
            const u64 p = pack2(ex2f(sl), ex2f(sh));
            s1d = add2(s1d, p);
            a1x = fma2(p, va.x, a1x);
            a1y = fma2(p, va.y, a1y);
            a1z = fma2(p, vc,   a1z);
        }
    }
    // loop B: i in [16, np2), q2-only, exit-only divergence
#pragma unroll 2
    for (int i = 16; i < np2; ++i) {
        const ulonglong2 ka = kA[w][i];
        const ulonglong2 kb = kB[w][i];
        const ulonglong2 va = vA[w][i];
        const u64 vc = vC[w][i];
        const u64 sc = fma2(Qd[1][0], ka.x, fma2(Qd[1][1], ka.y,
                       fma2(Qd[1][2], kb.x, mul2(Qd[1][3], kb.y))));
        float sl, sh; unpack2(sc, sl, sh);
        const u64 p = pack2(ex2f(sl), ex2f(sh));
        s2d = add2(s2d, p);
        a2x = fma2(p, va.x, a2x);
        a2y = fma2(p, va.y, a2y);
        a2z = fma2(p, vc,   a2z);
    }

    float lo, hi;
    unpack2(s1d, lo, hi); float sum1 = lo + hi;
    unpack2(a1x, lo, hi); float o1x = lo + hi;
    unpack2(a1y, lo, hi); float o1y = lo + hi;
    unpack2(a1z, lo, hi); float o1z = lo + hi;
    unpack2(s2d, lo, hi); float sum2 = lo + hi;
    unpack2(a2x, lo, hi); float o2x = lo + hi;
    unpack2(a2y, lo, hi); float o2y = lo + hi;
    unpack2(a2z, lo, hi); float o2z = lo + hi;

    // ---- self terms (even lane -> both tokens even) ----
    if (!(lane & 1)) {
#pragma unroll
        for (int tk = 0; tk < 2; ++tk) {
            const int t = lane + 32 * tk;
            const int i = t >> 1;
            const float* ka = (const float*)&kA[w][i];
            const float* kb = (const float*)&kB[w][i];
            const float* va = (const float*)&vA[w][i];
            const float* vc = (const float*)&vC[w][i];
            float Q0, Q1, Q2, Q3, d0, d1;
            unpack2(Qd[tk][0], Q0, d0); unpack2(Qd[tk][1], Q1, d0);
            unpack2(Qd[tk][2], Q2, d1); unpack2(Qd[tk][3], Q3, d1);
            const float sc = Q0*ka[0] + Q1*ka[2] + Q2*kb[0] + Q3*kb[2];
            const float p  = ex2f(sc);
            if (tk == 0) {
                sum1 += p; o1x += p*va[0]; o1y += p*va[2]; o1z += p*vc[0];
            } else {
                sum2 += p; o2x += p*va[0]; o2y += p*va[2]; o2z += p*vc[0];
            }
        }
    }

    // ---- epilogue: two tokens per lane ----
#pragma unroll
    for (int tk = 0; tk < 2; ++tk) {
        const int t = lane + 32 * tk;
        const float inv = rcpf(tk ? sum2 : sum1);
        const float a0 = (tk ? o2x : o1x) * inv;
        const float a1 = (tk ? o2y : o1y) * inv;
        const float a2 = (tk ? o2z : o1z) * inv;

        const float2 tkv = table_sh[digs[tk]];
        float x0 = tkv.x + a0;               // x += out@Wq (pre-folded)
        float x1 = tkv.y + a1;
        float x2 = __sinf((float)t * 1.0e-4f) + a2;

        float ms = (x0*x0 + x1*x1 + x2*x2) * (1.0f/3.0f) + 1e-6f;
        float r  = rsqrtf(ms);
        const float h0 = x0 * r * w_ln2[0];
        const float h1 = x1 * r * w_ln2[1];
        const float h2 = x2 * r * w_ln2[2];

        const float g0 = h0 * Wg[0] + h1 * Wg[1] + h2 * Wg[2];
        const float g1 = h0 * Wg[3] + h1 * Wg[4] + h2 * Wg[5];
        const float u0 = h0 * Wu[0] + h1 * Wu[1] + h2 * Wu[2];
        const float u1 = h0 * Wu[3] + h1 * Wu[4] + h2 * Wu[5];

        const float LOG2E = 1.4426950408889634f;
        const float m0 = g0 * u0 * rcpf(1.0f + ex2f(-g0 * LOG2E));
        const float m1 = g1 * u1 * rcpf(1.0f + ex2f(-g1 * LOG2E));

        x0 += m0 * Wd[0] + m1 * Wd[1];
        x1 += m0 * Wd[2] + m1 * Wd[3];
        x2 += m0 * Wd[4] + m1 * Wd[5];

        ms = (x0*x0 + x1*x1 + x2*x2) * (1.0f/3.0f) + 1e-6f;
        r  = rsqrtf(ms);
        const float f0 = x0 * r * w_lnf[0];
        const float f1 = x1 * r * w_lnf[1];

        float* lg = &logits_sh[(w * T + t) * VOCAB];
#pragma unroll
        for (int vv = 0; vv < VOCAB; ++vv) {
            const float2 tb = table_sh[vv];
            lg[vv] = f0 * tb.x + f1 * tb.y;
        }
    }
    __syncthreads();

    // ---- coalesced store: block owns a contiguous 5120-float span ----
    float2* dst2 = (float2*)(out + (size_t)blockIdx.x * (WPB * T * VOCAB));
    const float2* src2 = (const float2*)logits_sh;
#pragma unroll
    for (int i = tid; i < WPB * T * VOCAB / 2; i += NTHREADS)
        dst2[i] = src2[i];
}

extern "C" void kernel_launch(void* const* d_in, const int* in_sizes, int n_in,
                              void* d_out, int out_size)
{
    const int*   idx     = (const int*)  d_in[0];
    const float* arc_A   = (const float*)d_in[1];
    const float* arc_st  = (const float*)d_in[2];
    const float* arc_sd  = (const float*)d_in[3];
    const float* w_ln1   = (const float*)d_in[4];
    const float* w_ln2   = (const float*)d_in[5];
    const float* w_lnf   = (const float*)d_in[6];
    const float* w_qn    = (const float*)d_in[7];
    const float* Wq      = (const float*)d_in[8];
    const float* Wk      = (const float*)d_in[9];
    const float* Wg      = (const float*)d_in[10];
    const float* Wu      = (const float*)d_in[11];
    const float* Wd      = (const float*)d_in[12];
    float* out = (float*)d_out;

    precompute_kernel<<<VOCAB, T>>>(arc_A, arc_st, arc_sd, w_ln1, w_qn, Wq, Wk);

    const int B = in_sizes[0] / T;           // 16384
    const int grid = B / WPB;                // 2048 blocks
    adder_model_kernel<<<grid, NTHREADS>>>(idx, arc_A, arc_st, arc_sd,
                                           w_ln2, w_lnf, Wg, Wu, Wd, out);
}